// round 7
// baseline (speedup 1.0000x reference)
#include <cuda_runtime.h>
#include <cstdint>

#define BB 16384
#define TT 2048

// Scratch: x transposed to [T, B]; padded by one timestep so the prefetch of
// t+1 never branches (last prefetched value is read but never used).
__device__ float g_xT[(size_t)BB * (size_t)(TT + 1)];

typedef unsigned long long ull;

__device__ __forceinline__ ull pk2(float a, float b) {
    ull r; asm("mov.b64 %0, {%1, %2};" : "=l"(r) : "f"(a), "f"(b)); return r;
}
__device__ __forceinline__ void upk2(ull v, float& a, float& b) {
    asm("mov.b64 {%0, %1}, %2;" : "=f"(a), "=f"(b) : "l"(v));
}
__device__ __forceinline__ ull ffma2(ull a, ull b, ull c) {
    ull d; asm("fma.rn.f32x2 %0, %1, %2, %3;" : "=l"(d) : "l"(a), "l"(b), "l"(c)); return d;
}
// MUFU.TANH — single-instruction tanh (sm_75+)
__device__ __forceinline__ float tanh_mufu(float x) {
    float y; asm("tanh.approx.f32 %0, %1;" : "=f"(y) : "f"(x)); return y;
}
// sigmoid with the 0.5 input scale PRE-FOLDED into weights/biases:
// caller passes a = 0.5*(gi+gh); sigmoid = 0.5*tanh(a) + 0.5
__device__ __forceinline__ float sig_from_half(float a) {
    return fmaf(0.5f, tanh_mufu(a), 0.5f);
}

// ---------------------------------------------------------------------------
// Kernel 1: transpose x [B, T] -> g_xT [T, B]
// ---------------------------------------------------------------------------
__global__ void transpose_kernel(const float* __restrict__ x) {
    __shared__ float tile[32][33];
    int t0 = blockIdx.x * 32;
    int b0 = blockIdx.y * 32;
    int tx = threadIdx.x, ty = threadIdx.y;
#pragma unroll
    for (int i = 0; i < 4; i++) {
        tile[ty + i * 8][tx] = x[(size_t)(b0 + ty + i * 8) * TT + (t0 + tx)];
    }
    __syncthreads();
#pragma unroll
    for (int i = 0; i < 4; i++) {
        g_xT[(size_t)(t0 + ty + i * 8) * BB + (b0 + tx)] = tile[tx][ty + i * 8];
    }
}

// ---------------------------------------------------------------------------
// Kernel 2: GRU scan, 16-way hidden split, k-packed f32x2 dots, 4 elems/group,
//           sized for EXACTLY ONE WAVE (2048 warps, 7 blocks/SM of 2 warps).
//   - Lane j (= tid&15) owns hidden index j and gate rows {j,16+j,32+j}.
//     Weights k-packed (w_2m, w_2m+1): 24 ull = 48 regs, stored ONCE.
//   - Group of 16 lanes processes 4 batch elements; per element the dot is a
//     packed f32x2 accumulation over 8 chunks + one horizontal add per gate.
//     4 independent chains per gate -> ILP covers FMA latency.
//   - h kept in SMEM (20-float padded slots, broadcast LDS.128 reads,
//     conflict-free writes), double-buffered, one __syncwarp per step.
//   - r/z weights+biases pre-scaled by 0.5 (sigmoid via tanh identity).
// ---------------------------------------------------------------------------

#define NE 4      // batch elements per 16-lane group
#define SLOT 20   // floats per element h slot (16 + 4 pad)

__global__ __launch_bounds__(64, 7)
void gru_kernel(const float* __restrict__ w_ih, const float* __restrict__ w_hh,
                const float* __restrict__ b_ih, const float* __restrict__ b_hh,
                const float* __restrict__ w_fc, const float* __restrict__ b_fc,
                float* __restrict__ out)
{
    __shared__ float hbuf[2][4][NE][SLOT];   // [buf][group-in-block][elem][h]

    int tid = threadIdx.x;
    int j   = tid & 15;                       // owned hidden index
    int grp = tid >> 4;                       // group within block (0..3)
    int gid = (blockIdx.x * 64 + tid) >> 4;   // global group; elements 4gid..4gid+3

    // --- k-packed register weights: 8 ull per gate row ---
    ull wr2[8], wz2[8], wn2[8];
#pragma unroll
    for (int m = 0; m < 8; m++) {
        wr2[m] = pk2(0.5f * __ldg(&w_hh[j * 16 + 2 * m]),
                     0.5f * __ldg(&w_hh[j * 16 + 2 * m + 1]));
        wz2[m] = pk2(0.5f * __ldg(&w_hh[(16 + j) * 16 + 2 * m]),
                     0.5f * __ldg(&w_hh[(16 + j) * 16 + 2 * m + 1]));
        wn2[m] = pk2(__ldg(&w_hh[(32 + j) * 16 + 2 * m]),
                     __ldg(&w_hh[(32 + j) * 16 + 2 * m + 1]));
    }

    // --- scalar gate-input constants ---
    float wirf = 0.5f * __ldg(&w_ih[j]);
    float wizf = 0.5f * __ldg(&w_ih[16 + j]);
    float winf = __ldg(&w_ih[32 + j]);
    float bsrf = 0.5f * (__ldg(&b_ih[j]) + __ldg(&b_hh[j]));
    float bszf = 0.5f * (__ldg(&b_ih[16 + j]) + __ldg(&b_hh[16 + j]));
    float binf = __ldg(&b_ih[32 + j]);
    float bhnf = __ldg(&b_hh[32 + j]);

    float hown[NE];
#pragma unroll
    for (int e = 0; e < NE; e++) {
        hown[e] = 0.0f;
        hbuf[0][grp][e][j] = 0.0f;            // zero initial h (buf 0 only)
    }
    __syncwarp();

    const float4* xp = ((const float4*)g_xT) + gid;
    float4 xv = __ldg(xp);
    xp += (BB / 4);

    int buf = 0;
    for (int t = 0; t < TT; t++) {
        float4 xnext = __ldg(xp);             // padded array: always valid
        xp += (BB / 4);
        float xe[NE] = {xv.x, xv.y, xv.z, xv.w};

        // packed accumulators: halves sum to the pre-activation
        ull aR[NE], aZ[NE], aN[NE];
#pragma unroll
        for (int e = 0; e < NE; e++) {
            aR[e] = pk2(fmaf(xe[e], wirf, bsrf), 0.0f);
            aZ[e] = pk2(fmaf(xe[e], wizf, bszf), 0.0f);
            aN[e] = pk2(bhnf, 0.0f);
        }

        // dot phase: stream h from SMEM (broadcast within group)
#pragma unroll
        for (int c = 0; c < 4; c++) {
#pragma unroll
            for (int e = 0; e < NE; e++) {
                ulonglong2 v = *(const ulonglong2*)&hbuf[buf][grp][e][4 * c];
                aR[e] = ffma2(wr2[2 * c], v.x, aR[e]);
                aZ[e] = ffma2(wz2[2 * c], v.x, aZ[e]);
                aN[e] = ffma2(wn2[2 * c], v.x, aN[e]);
                aR[e] = ffma2(wr2[2 * c + 1], v.y, aR[e]);
                aZ[e] = ffma2(wz2[2 * c + 1], v.y, aZ[e]);
                aN[e] = ffma2(wn2[2 * c + 1], v.y, aN[e]);
            }
        }

        // tails: 4 independent scalar chains
        int nbuf = buf ^ 1;
#pragma unroll
        for (int e = 0; e < NE; e++) {
            float lo, hi;
            upk2(aR[e], lo, hi);
            float r = sig_from_half(lo + hi);
            upk2(aZ[e], lo, hi);
            float z = sig_from_half(lo + hi);
            upk2(aN[e], lo, hi);
            float gh  = lo + hi;
            float gi  = fmaf(xe[e], winf, binf);
            float n   = tanh_mufu(fmaf(r, gh, gi));
            float h   = fmaf(z, hown[e] - n, n);     // (1-z)n + z h
            hown[e] = h;
            hbuf[nbuf][grp][e][j] = h;
        }
        __syncwarp();
        buf = nbuf;

        xv = xnext;
    }

    // FC epilogue: out[b] = sum_j h[b][j] * w_fc[j] + b_fc  (reduce over 16 lanes)
    float wf = __ldg(&w_fc[j]);
    float s[NE];
#pragma unroll
    for (int e = 0; e < NE; e++) s[e] = hown[e] * wf;
#pragma unroll
    for (int d = 1; d < 16; d <<= 1) {
#pragma unroll
        for (int e = 0; e < NE; e++) {
            s[e] += __shfl_xor_sync(0xffffffffu, s[e], d);
        }
    }
    if (j == 0) {
        float bf = __ldg(b_fc);
        float4 o;
        o.x = s[0] + bf;
        o.y = s[1] + bf;
        o.z = s[2] + bf;
        o.w = s[3] + bf;
        *(float4*)(out + 4 * gid) = o;
    }
}

// ---------------------------------------------------------------------------
extern "C" void kernel_launch(void* const* d_in, const int* in_sizes, int n_in,
                              void* d_out, int out_size)
{
    const float* x    = (const float*)d_in[0];
    const float* w_ih = (const float*)d_in[1];
    const float* w_hh = (const float*)d_in[2];
    const float* b_ih = (const float*)d_in[3];
    const float* b_hh = (const float*)d_in[4];
    const float* w_fc = (const float*)d_in[5];
    const float* b_fc = (const float*)d_in[6];
    float* out = (float*)d_out;

    dim3 tb(32, 8);
    dim3 tg(TT / 32, BB / 32);
    transpose_kernel<<<tg, tb>>>(x);

    // 16384 elems / 4 per 16-lane group * 16 lanes = 65536 threads
    // = 1024 blocks x 64 threads = 2048 warps -> ONE wave at 7 blocks/SM.
    gru_kernel<<<1024, 64>>>(w_ih, w_hh, b_ih, b_hh, w_fc, b_fc, out);
}